// round 6
// baseline (speedup 1.0000x reference)
#include <cuda_runtime.h>
#include <cuda_bf16.h>
#include <math.h>

// ---------------------------------------------------------------------------
// Problem constants
// ---------------------------------------------------------------------------
#define TT   2048
#define DD   3584
#define NH   28
#define KVH  4
#define HD   128
#define GRP  7              // NH / KVH
#define KVW  (KVH*HD)       // 512
#define QW   (NH*HD)        // 3584

// ---------------------------------------------------------------------------
// Device scratch (no allocation allowed)
// ---------------------------------------------------------------------------
__device__ float g_q [TT * QW];
__device__ float g_k [TT * KVW];
__device__ float g_v [TT * KVW];
__device__ float g_ao[TT * QW];

// ---------------------------------------------------------------------------
// Classic 128x128x8 SGEMM, A[M,K] row-major, B[K,N] row-major, optional bias[N]
// 256 threads, 8x8 micro-tile per thread.
// ---------------------------------------------------------------------------
#define BM 128
#define BN 128
#define BK 8

__global__ __launch_bounds__(256, 2)
void sgemm_bias_kernel(const float* __restrict__ A, const float* __restrict__ B,
                       const float* __restrict__ bias, float* __restrict__ C,
                       int M, int N, int K)
{
    __shared__ float As[BK][BM];
    __shared__ float Bs[BK][BN];

    const int tid = threadIdx.x;
    const int tx  = tid & 15;
    const int ty  = tid >> 4;

    const float* Ab = A + (size_t)blockIdx.y * BM * K;
    const float* Bb = B + (size_t)blockIdx.x * BN;

    const int aRow = tid >> 1;
    const int aCol = (tid & 1) * 4;
    const int bRow = tid >> 5;
    const int bCol = (tid & 31) * 4;

    float acc[8][8];
    #pragma unroll
    for (int i = 0; i < 8; i++)
        #pragma unroll
        for (int j = 0; j < 8; j++) acc[i][j] = 0.f;

    for (int k0 = 0; k0 < K; k0 += BK) {
        float4 a = *(const float4*)(Ab + (size_t)aRow * K + k0 + aCol);
        As[aCol + 0][aRow] = a.x;
        As[aCol + 1][aRow] = a.y;
        As[aCol + 2][aRow] = a.z;
        As[aCol + 3][aRow] = a.w;
        *(float4*)(&Bs[bRow][bCol]) =
            *(const float4*)(Bb + (size_t)(k0 + bRow) * N + bCol);
        __syncthreads();

        #pragma unroll
        for (int kk = 0; kk < BK; kk++) {
            float ar[8], br[8];
            *(float4*)(ar)     = *(float4*)(&As[kk][ty * 8]);
            *(float4*)(ar + 4) = *(float4*)(&As[kk][ty * 8 + 4]);
            *(float4*)(br)     = *(float4*)(&Bs[kk][tx * 8]);
            *(float4*)(br + 4) = *(float4*)(&Bs[kk][tx * 8 + 4]);
            #pragma unroll
            for (int i = 0; i < 8; i++)
                #pragma unroll
                for (int j = 0; j < 8; j++)
                    acc[i][j] += ar[i] * br[j];
        }
        __syncthreads();
    }

    float bj[8];
    #pragma unroll
    for (int j = 0; j < 8; j++)
        bj[j] = bias ? bias[blockIdx.x * BN + tx * 8 + j] : 0.f;

    #pragma unroll
    for (int i = 0; i < 8; i++) {
        const size_t row = (size_t)blockIdx.y * BM + ty * 8 + i;
        float* crow = C + row * N + blockIdx.x * BN + tx * 8;
        float4 v0, v1;
        v0.x = acc[i][0] + bj[0]; v0.y = acc[i][1] + bj[1];
        v0.z = acc[i][2] + bj[2]; v0.w = acc[i][3] + bj[3];
        v1.x = acc[i][4] + bj[4]; v1.y = acc[i][5] + bj[5];
        v1.z = acc[i][6] + bj[6]; v1.w = acc[i][7] + bj[7];
        *(float4*)(crow)     = v0;
        *(float4*)(crow + 4) = v1;
    }
}

// ---------------------------------------------------------------------------
// RoPE (in-place). One thread per (t, head, pair i<64).
// ---------------------------------------------------------------------------
__global__ void rope_kernel(float* __restrict__ buf,
                            const float* __restrict__ sinT,
                            const float* __restrict__ cosT,
                            int nheads)
{
    int idx = blockIdx.x * blockDim.x + threadIdx.x;
    int total = TT * nheads * (HD / 2);
    if (idx >= total) return;
    int i = idx & 63;
    int h = (idx >> 6) % nheads;
    int t = idx / (64 * nheads);

    float* p = buf + (size_t)t * (nheads * HD) + h * HD;
    float x1 = p[i];
    float x2 = p[i + 64];
    float s = sinT[t * 64 + i];
    float c = cosT[t * 64 + i];
    p[i]      = x1 * c - x2 * s;
    p[i + 64] = x2 * c + x1 * s;
}

// ---------------------------------------------------------------------------
// Flash attention (fp32, causal, GQA). Tile 64 queries x 64 keys, H=128.
// 256 threads = 16x16; S micro-tile 4x4 per thread; O micro-tile 4x8.
// Q,K stored transposed in smem ([H][64+pad]) for conflict-free LDS.128.
// ---------------------------------------------------------------------------
#define AT_BM 64
#define AT_BN 64
#define QK_PITCH 68   // 64 + 4 pad, keeps rows 16B-aligned

#define ATT_SMEM_FLOATS (2 * HD * QK_PITCH + AT_BN * HD + AT_BM * AT_BN)

__global__ __launch_bounds__(256, 1)
void attn_kernel(const float* __restrict__ qb, const float* __restrict__ kb,
                 const float* __restrict__ vb, float* __restrict__ ob)
{
    extern __shared__ float sm[];
    float* Qst = sm;                         // [128][QK_PITCH]
    float* Kst = Qst + HD * QK_PITCH;        // [128][QK_PITCH]
    float* Vs  = Kst + HD * QK_PITCH;        // [64][128]
    float* Ps  = Vs  + AT_BN * HD;           // [64][64]

    const int tid = threadIdx.x;
    const int tx  = tid & 15;
    const int ty  = tid >> 4;
    const int qi  = blockIdx.x;          // query block
    const int n   = blockIdx.y;          // head
    const int kh  = n / GRP;
    const int q0  = qi * AT_BM;

    // load Q tile transposed
    #pragma unroll
    for (int it = 0; it < 8; it++) {
        int idx = (it * 256 + tid) * 4;
        int row = idx >> 7;
        int h   = idx & 127;
        float4 v = *(const float4*)(qb + (size_t)(q0 + row) * QW + n * HD + h);
        Qst[(h + 0) * QK_PITCH + row] = v.x;
        Qst[(h + 1) * QK_PITCH + row] = v.y;
        Qst[(h + 2) * QK_PITCH + row] = v.z;
        Qst[(h + 3) * QK_PITCH + row] = v.w;
    }

    float m_reg[4], l_reg[4], acc[4][8];
    #pragma unroll
    for (int i = 0; i < 4; i++) {
        m_reg[i] = -1e30f; l_reg[i] = 0.f;
        #pragma unroll
        for (int j = 0; j < 8; j++) acc[i][j] = 0.f;
    }

    const float scale = 0.08838834764831845f;   // 1/sqrt(128)

    for (int kbk = 0; kbk <= qi; kbk++) {
        const int k0 = kbk * AT_BN;
        __syncthreads();   // previous iteration consumers done

        // load K (transposed) and V
        #pragma unroll
        for (int it = 0; it < 8; it++) {
            int idx = (it * 256 + tid) * 4;
            int row = idx >> 7;
            int h   = idx & 127;
            float4 vk = *(const float4*)(kb + (size_t)(k0 + row) * KVW + kh * HD + h);
            Kst[(h + 0) * QK_PITCH + row] = vk.x;
            Kst[(h + 1) * QK_PITCH + row] = vk.y;
            Kst[(h + 2) * QK_PITCH + row] = vk.z;
            Kst[(h + 3) * QK_PITCH + row] = vk.w;
            float4 vv = *(const float4*)(vb + (size_t)(k0 + row) * KVW + kh * HD + h);
            *(float4*)(Vs + row * HD + h) = vv;
        }
        __syncthreads();

        // S = Q K^T  (4x4 per thread)
        float s[4][4];
        #pragma unroll
        for (int i = 0; i < 4; i++)
            #pragma unroll
            for (int j = 0; j < 4; j++) s[i][j] = 0.f;

        #pragma unroll 8
        for (int kk = 0; kk < HD; kk++) {
            float4 qr = *(float4*)(Qst + kk * QK_PITCH + ty * 4);
            float4 kr = *(float4*)(Kst + kk * QK_PITCH + tx * 4);
            s[0][0] += qr.x * kr.x; s[0][1] += qr.x * kr.y; s[0][2] += qr.x * kr.z; s[0][3] += qr.x * kr.w;
            s[1][0] += qr.y * kr.x; s[1][1] += qr.y * kr.y; s[1][2] += qr.y * kr.z; s[1][3] += qr.y * kr.w;
            s[2][0] += qr.z * kr.x; s[2][1] += qr.z * kr.y; s[2][2] += qr.z * kr.z; s[2][3] += qr.z * kr.w;
            s[3][0] += qr.w * kr.x; s[3][1] += qr.w * kr.y; s[3][2] += qr.w * kr.z; s[3][3] += qr.w * kr.w;
        }

        // scale + causal mask + online softmax update
        #pragma unroll
        for (int i = 0; i < 4; i++) {
            const int gq = q0 + ty * 4 + i;
            float rmax = -1e30f;
            #pragma unroll
            for (int j = 0; j < 4; j++) {
                int gk = k0 + tx * 4 + j;
                float sv = s[i][j] * scale;
                if (gk > gq) sv = -1e30f;
                s[i][j] = sv;
                rmax = fmaxf(rmax, sv);
            }
            // reduce max across the 16 lanes that share this row
            #pragma unroll
            for (int off = 8; off > 0; off >>= 1)
                rmax = fmaxf(rmax, __shfl_xor_sync(0xffffffffu, rmax, off));

            float m_new = fmaxf(m_reg[i], rmax);
            float alpha = __expf(m_reg[i] - m_new);

            float rsum = 0.f;
            #pragma unroll
            for (int j = 0; j < 4; j++) {
                float p = __expf(s[i][j] - m_new);
                s[i][j] = p;
                rsum += p;
            }
            #pragma unroll
            for (int off = 8; off > 0; off >>= 1)
                rsum += __shfl_xor_sync(0xffffffffu, rsum, off);

            l_reg[i] = l_reg[i] * alpha + rsum;
            m_reg[i] = m_new;

            #pragma unroll
            for (int j = 0; j < 8; j++) acc[i][j] *= alpha;

            #pragma unroll
            for (int j = 0; j < 4; j++)
                Ps[(ty * 4 + i) * AT_BN + tx * 4 + j] = s[i][j];
        }
        __syncthreads();

        // O += P @ V  (4 rows x 8 cols per thread)
        #pragma unroll 4
        for (int kk = 0; kk < AT_BN; kk++) {
            float4 v0 = *(float4*)(Vs + kk * HD + tx * 8);
            float4 v1 = *(float4*)(Vs + kk * HD + tx * 8 + 4);
            float p0 = Ps[(ty * 4 + 0) * AT_BN + kk];
            float p1 = Ps[(ty * 4 + 1) * AT_BN + kk];
            float p2 = Ps[(ty * 4 + 2) * AT_BN + kk];
            float p3 = Ps[(ty * 4 + 3) * AT_BN + kk];
            acc[0][0] += p0 * v0.x; acc[0][1] += p0 * v0.y; acc[0][2] += p0 * v0.z; acc[0][3] += p0 * v0.w;
            acc[0][4] += p0 * v1.x; acc[0][5] += p0 * v1.y; acc[0][6] += p0 * v1.z; acc[0][7] += p0 * v1.w;
            acc[1][0] += p1 * v0.x; acc[1][1] += p1 * v0.y; acc[1][2] += p1 * v0.z; acc[1][3] += p1 * v0.w;
            acc[1][4] += p1 * v1.x; acc[1][5] += p1 * v1.y; acc[1][6] += p1 * v1.z; acc[1][7] += p1 * v1.w;
            acc[2][0] += p2 * v0.x; acc[2][1] += p2 * v0.y; acc[2][2] += p2 * v0.z; acc[2][3] += p2 * v0.w;
            acc[2][4] += p2 * v1.x; acc[2][5] += p2 * v1.y; acc[2][6] += p2 * v1.z; acc[2][7] += p2 * v1.w;
            acc[3][0] += p3 * v0.x; acc[3][1] += p3 * v0.y; acc[3][2] += p3 * v0.z; acc[3][3] += p3 * v0.w;
            acc[3][4] += p3 * v1.x; acc[3][5] += p3 * v1.y; acc[3][6] += p3 * v1.z; acc[3][7] += p3 * v1.w;
        }
    }

    // epilogue: O / l
    #pragma unroll
    for (int i = 0; i < 4; i++) {
        float inv = 1.f / l_reg[i];
        const size_t row = q0 + ty * 4 + i;
        float* orow = ob + row * QW + n * HD + tx * 8;
        float4 v0, v1;
        v0.x = acc[i][0] * inv; v0.y = acc[i][1] * inv;
        v0.z = acc[i][2] * inv; v0.w = acc[i][3] * inv;
        v1.x = acc[i][4] * inv; v1.y = acc[i][5] * inv;
        v1.z = acc[i][6] * inv; v1.w = acc[i][7] * inv;
        *(float4*)(orow)     = v0;
        *(float4*)(orow + 4) = v1;
    }
}

// ---------------------------------------------------------------------------
// Launch
//   inputs: 0:x 1:attn_mask 2:sin 3:cos 4:wq 5:wk 6:wv 7:wo 8:q_bias 9:k_bias 10:v_bias
// ---------------------------------------------------------------------------
extern "C" void kernel_launch(void* const* d_in, const int* in_sizes, int n_in,
                              void* d_out, int out_size)
{
    const float* x      = (const float*)d_in[0];
    const float* sinT   = (const float*)d_in[2];
    const float* cosT   = (const float*)d_in[3];
    const float* wq     = (const float*)d_in[4];
    const float* wk     = (const float*)d_in[5];
    const float* wv     = (const float*)d_in[6];
    const float* wo     = (const float*)d_in[7];
    const float* q_bias = (const float*)d_in[8];
    const float* k_bias = (const float*)d_in[9];
    const float* v_bias = (const float*)d_in[10];
    float* out = (float*)d_out;

    float *qp, *kp, *vp, *aop;
    cudaGetSymbolAddress((void**)&qp,  g_q);
    cudaGetSymbolAddress((void**)&kp,  g_k);
    cudaGetSymbolAddress((void**)&vp,  g_v);
    cudaGetSymbolAddress((void**)&aop, g_ao);

    // QKV projections (+bias)
    {
        dim3 grid(QW / BN, TT / BM);
        sgemm_bias_kernel<<<grid, 256>>>(x, wq, q_bias, qp, TT, QW, DD);
    }
    {
        dim3 grid(KVW / BN, TT / BM);
        sgemm_bias_kernel<<<grid, 256>>>(x, wk, k_bias, kp, TT, KVW, DD);
        sgemm_bias_kernel<<<grid, 256>>>(x, wv, v_bias, vp, TT, KVW, DD);
    }

    // RoPE
    {
        int totq = TT * NH * (HD / 2);
        rope_kernel<<<(totq + 255) / 256, 256>>>(qp, sinT, cosT, NH);
        int totk = TT * KVH * (HD / 2);
        rope_kernel<<<(totk + 255) / 256, 256>>>(kp, sinT, cosT, KVH);
    }

    // Attention
    {
        const size_t smem = ATT_SMEM_FLOATS * sizeof(float);
        cudaFuncSetAttribute(attn_kernel,
                             cudaFuncAttributeMaxDynamicSharedMemorySize,
                             (int)smem);
        dim3 grid(TT / AT_BM, NH);
        attn_kernel<<<grid, 256, smem>>>(qp, kp, vp, aop);
    }

    // Output projection
    {
        dim3 grid(QW / BN, TT / BM);
        sgemm_bias_kernel<<<grid, 256>>>(aop, wo, nullptr, out, TT, QW, DD);
    }
}